// round 8
// baseline (speedup 1.0000x reference)
#include <cuda_runtime.h>

// TritonDualLIF: x [T=16,B=32,N=196,C=512] f32, decay scalar.
// v = d*v + x[t]; vpool[t,b,c] = mean_n(pre-reset v); s = (v>=1); v = s?0:v.
// out = spikes [T,B,N,C] ++ vpool [T,B,C].
//
// float2 lanes, N split into 4 chunks of 49; 1024 CTAs. Inner loop: 6
// uniform iterations (48 rows) + 1 predicated row (ty==0). occ target 5/SM.
// Last-arriving CTA of each 4-chunk group combines partials -> vpool.

#define T_ 16
#define B_ 32
#define N_ 196
#define C_ 512
#define C2 (C_ / 2)        // 256 float2 per row
#define NH 4
#define NSUB 49
#define NLANES 8
#define JFULL 6            // uniform: rows ty + 8j, j=0..5 -> 48 rows
#define NGROUP 256         // B_ * (C2/32) = 32 * 8

// Per-chunk partial sums: [NH][group][T*32] float2 = 4 MB.
__device__ float2   g_part[NH * NGROUP * T_ * 32];
__device__ unsigned g_ctr[NGROUP];   // parity mod 4 elects the combiner

__global__ __launch_bounds__(256, 5)
void lif_dual_kernel(const float2* __restrict__ x,
                     const float* __restrict__ decay,
                     float* __restrict__ out) {
    const int tx   = threadIdx.x;     // c2 lane 0..31
    const int ty   = threadIdx.y;     // n lane 0..7
    const int cblk = blockIdx.x;      // 0..7
    const int b    = blockIdx.y;      // 0..31
    const int z    = blockIdx.z;      // 0..3  (N chunk)
    const float d  = decay[0];

    float2* __restrict__ spikes = (float2*)out;
    float2* __restrict__ vpool  = (float2*)(out + (size_t)T_ * B_ * N_ * C_);

    __shared__ float2 red[NLANES][T_][32];  // exclusive slots, no in-loop sync
    __shared__ int    s_last;

    float2 v[JFULL + 1];
#pragma unroll
    for (int j = 0; j <= JFULL; ++j) v[j] = make_float2(0.f, 0.f);

    const unsigned c2      = (unsigned)cblk * 32u + (unsigned)tx;
    const unsigned bbase   = (unsigned)b * (N_ * C2)
                           + (unsigned)(z * NSUB + ty) * C2 + c2;
    const unsigned tstride = (unsigned)(B_ * N_ * C2);
    const bool extra = (ty == 0);     // row 48 of this chunk

    for (int t = 0; t < T_; ++t) {
        const unsigned tb = (unsigned)t * tstride + bbase;
        float2 part = make_float2(0.f, 0.f);
#pragma unroll
        for (int j = 0; j < JFULL; ++j) {
            const unsigned idx = tb + (unsigned)(j * (NLANES * C2));
            const float2 xv = x[idx];
            float2 vv;
            vv.x = fmaf(d, v[j].x, xv.x);
            vv.y = fmaf(d, v[j].y, xv.y);
            part.x += vv.x;                   // pre-reset membrane
            part.y += vv.y;
            const bool fx = (vv.x >= 1.0f);
            const bool fy = (vv.y >= 1.0f);
            float2 s;
            s.x = fx ? 1.0f : 0.0f;
            s.y = fy ? 1.0f : 0.0f;
            spikes[idx] = s;
            v[j].x = fx ? 0.0f : vv.x;        // hard reset
            v[j].y = fy ? 0.0f : vv.y;
        }
        if (extra) {
            const unsigned idx = tb + (unsigned)(JFULL * (NLANES * C2));
            const float2 xv = x[idx];
            float2 vv;
            vv.x = fmaf(d, v[JFULL].x, xv.x);
            vv.y = fmaf(d, v[JFULL].y, xv.y);
            part.x += vv.x;
            part.y += vv.y;
            const bool fx = (vv.x >= 1.0f);
            const bool fy = (vv.y >= 1.0f);
            float2 s;
            s.x = fx ? 1.0f : 0.0f;
            s.y = fy ? 1.0f : 0.0f;
            spikes[idx] = s;
            v[JFULL].x = fx ? 0.0f : vv.x;
            v[JFULL].y = fy ? 0.0f : vv.y;
        }
        red[ty][t][tx] = part;                // exclusive slot
    }

    __syncthreads();

    // Reduce 8 lanes -> chunk partial [T_*32] float2, store to scratch.
    const int tid   = ty * 32 + tx;
    const int group = b * 8 + cblk;           // 0..255
    float2* gp = &g_part[((unsigned)z * NGROUP + (unsigned)group) * (T_ * 32)];
#pragma unroll
    for (int o = 0; o < 2; ++o) {
        const int oi = tid + o * 256;         // 0..511
        const int t  = oi >> 5;
        const int cc = oi & 31;
        float2 sum = red[0][t][cc];
#pragma unroll
        for (int k = 1; k < NLANES; ++k) {
            sum.x += red[k][t][cc].x;
            sum.y += red[k][t][cc].y;
        }
        gp[oi] = sum;
    }

    __threadfence();
    __syncthreads();
    if (tid == 0) {
        const unsigned old = atomicAdd(&g_ctr[group], 1u);
        s_last = ((old & 3u) == 3u) ? 1 : 0;
    }
    __syncthreads();

    if (s_last) {
        __threadfence();   // acquire: see all chunks' scratch writes
        const float2* p0 = &g_part[((unsigned)group) * (T_ * 32)];
        const float2* p1 = &g_part[((unsigned)(NGROUP + group)) * (T_ * 32)];
        const float2* p2 = &g_part[((unsigned)(2 * NGROUP + group)) * (T_ * 32)];
        const float2* p3 = &g_part[((unsigned)(3 * NGROUP + group)) * (T_ * 32)];
#pragma unroll
        for (int o = 0; o < 2; ++o) {
            const int oi = tid + o * 256;
            const int t  = oi >> 5;
            const int cc = oi & 31;
            float2 r;
            r.x = ((p0[oi].x + p1[oi].x) + (p2[oi].x + p3[oi].x)) * (1.0f / (float)N_);
            r.y = ((p0[oi].y + p1[oi].y) + (p2[oi].y + p3[oi].y)) * (1.0f / (float)N_);
            vpool[(unsigned)t * (B_ * C2) + (unsigned)b * C2
                  + (unsigned)cblk * 32u + (unsigned)cc] = r;
        }
    }
}

extern "C" void kernel_launch(void* const* d_in, const int* in_sizes, int n_in,
                              void* d_out, int out_size) {
    const float2* x    = (const float2*)d_in[0];
    const float* decay = (const float*)d_in[1];
    float* out = (float*)d_out;

    dim3 block(32, NLANES);             // 256 threads
    dim3 grid(C2 / 32, B_, NH);         // 8 x 32 x 4 = 1024 blocks
    lif_dual_kernel<<<grid, block>>>(x, decay, out);
}

// round 9
// speedup vs baseline: 1.1171x; 1.1171x over previous
#include <cuda_runtime.h>

// TritonDualLIF: x [T=16,B=32,N=196,C=512] f32, decay scalar.
// v = d*v + x[t]; vpool[t,b,c] = mean_n(pre-reset v); s = (v>=1); v = s?0:v.
// out = spikes [T,B,N,C] ++ vpool [T,B,C].
//
// R6 structure (float2, NH=4 chunks of 49, 1024 CTAs) + software-pipelined
// register prefetch of timestep t+1's x while computing t. occ 3, 80-reg cap.

#define T_ 16
#define B_ 32
#define N_ 196
#define C_ 512
#define C2 (C_ / 2)        // 256 float2 per row
#define NH 4
#define NSUB 49
#define NLANES 8
#define JMAX 7             // ty==0 -> 7 rows, else 6
#define NGROUP 256         // B_ * (C2/32)

// Per-chunk partial sums: [NH][group][T*32] float2 = 4 MB.
__device__ float2   g_part[NH * NGROUP * T_ * 32];
__device__ unsigned g_ctr[NGROUP];   // parity mod 4 elects the combiner

__global__ __launch_bounds__(256, 3)
void lif_dual_kernel(const float2* __restrict__ x,
                     const float* __restrict__ decay,
                     float* __restrict__ out) {
    const int tx   = threadIdx.x;     // c2 lane 0..31
    const int ty   = threadIdx.y;     // n lane 0..7
    const int cblk = blockIdx.x;      // 0..7
    const int b    = blockIdx.y;      // 0..31
    const int z    = blockIdx.z;      // 0..3  (N chunk)
    const float d  = decay[0];

    float2* __restrict__ spikes = (float2*)out;
    float2* __restrict__ vpool  = (float2*)(out + (size_t)T_ * B_ * N_ * C_);

    __shared__ float2 red[NLANES][T_][32];  // exclusive slots, no in-loop sync
    __shared__ int    s_last;

    float2 v[JMAX];
    float2 xc[JMAX];                        // current timestep's inputs
#pragma unroll
    for (int j = 0; j < JMAX; ++j) v[j] = make_float2(0.f, 0.f);

    const unsigned c2      = (unsigned)cblk * 32u + (unsigned)tx;
    const unsigned bbase   = (unsigned)b * (N_ * C2)
                           + (unsigned)(z * NSUB + ty) * C2 + c2;
    const unsigned tstride = (unsigned)(B_ * N_ * C2);
    const int jcnt = (ty == 0) ? JMAX : (JMAX - 1);

    // Prologue: load t=0 inputs.
#pragma unroll
    for (int j = 0; j < JMAX; ++j)
        if (j < jcnt) xc[j] = x[bbase + (unsigned)(j * (NLANES * C2))];

    for (int t = 0; t < T_; ++t) {
        const unsigned tb = (unsigned)t * tstride + bbase;

        // Prefetch t+1 BEFORE consuming t (keeps ~12 loads in flight).
        float2 xn[JMAX];
        if (t + 1 < T_) {
            const unsigned nb = tb + tstride;
#pragma unroll
            for (int j = 0; j < JMAX; ++j)
                if (j < jcnt) xn[j] = x[nb + (unsigned)(j * (NLANES * C2))];
        }

        float2 part = make_float2(0.f, 0.f);
#pragma unroll
        for (int j = 0; j < JMAX; ++j) {
            if (j < jcnt) {
                const unsigned idx = tb + (unsigned)(j * (NLANES * C2));
                float2 vv;
                vv.x = fmaf(d, v[j].x, xc[j].x);
                vv.y = fmaf(d, v[j].y, xc[j].y);
                part.x += vv.x;                   // pre-reset membrane
                part.y += vv.y;
                const bool fx = (vv.x >= 1.0f);
                const bool fy = (vv.y >= 1.0f);
                float2 s;
                s.x = fx ? 1.0f : 0.0f;
                s.y = fy ? 1.0f : 0.0f;
                spikes[idx] = s;
                v[j].x = fx ? 0.0f : vv.x;        // hard reset
                v[j].y = fy ? 0.0f : vv.y;
            }
        }
        red[ty][t][tx] = part;                    // exclusive slot

#pragma unroll
        for (int j = 0; j < JMAX; ++j) xc[j] = xn[j];
    }

    __syncthreads();

    // Reduce 8 lanes -> chunk partial [T_*32] float2, store to scratch.
    const int tid   = ty * 32 + tx;
    const int group = b * 8 + cblk;               // 0..255
    float2* gp = &g_part[((unsigned)z * NGROUP + (unsigned)group) * (T_ * 32)];
#pragma unroll
    for (int o = 0; o < 2; ++o) {
        const int oi = tid + o * 256;             // 0..511
        const int t  = oi >> 5;
        const int cc = oi & 31;
        float2 sum = red[0][t][cc];
#pragma unroll
        for (int k = 1; k < NLANES; ++k) {
            sum.x += red[k][t][cc].x;
            sum.y += red[k][t][cc].y;
        }
        gp[oi] = sum;
    }

    __threadfence();
    __syncthreads();
    if (tid == 0) {
        const unsigned old = atomicAdd(&g_ctr[group], 1u);
        s_last = ((old & 3u) == 3u) ? 1 : 0;
    }
    __syncthreads();

    if (s_last) {
        __threadfence();   // acquire: see all chunks' scratch writes
        const float2* p0 = &g_part[((unsigned)group) * (T_ * 32)];
        const float2* p1 = &g_part[((unsigned)(NGROUP + group)) * (T_ * 32)];
        const float2* p2 = &g_part[((unsigned)(2 * NGROUP + group)) * (T_ * 32)];
        const float2* p3 = &g_part[((unsigned)(3 * NGROUP + group)) * (T_ * 32)];
#pragma unroll
        for (int o = 0; o < 2; ++o) {
            const int oi = tid + o * 256;
            const int t  = oi >> 5;
            const int cc = oi & 31;
            float2 r;
            r.x = ((p0[oi].x + p1[oi].x) + (p2[oi].x + p3[oi].x)) * (1.0f / (float)N_);
            r.y = ((p0[oi].y + p1[oi].y) + (p2[oi].y + p3[oi].y)) * (1.0f / (float)N_);
            vpool[(unsigned)t * (B_ * C2) + (unsigned)b * C2
                  + (unsigned)cblk * 32u + (unsigned)cc] = r;
        }
    }
}

extern "C" void kernel_launch(void* const* d_in, const int* in_sizes, int n_in,
                              void* d_out, int out_size) {
    const float2* x    = (const float2*)d_in[0];
    const float* decay = (const float*)d_in[1];
    float* out = (float*)d_out;

    dim3 block(32, NLANES);             // 256 threads
    dim3 grid(C2 / 32, B_, NH);         // 8 x 32 x 4 = 1024 blocks
    lif_dual_kernel<<<grid, block>>>(x, decay, out);
}

// round 10
// speedup vs baseline: 1.1236x; 1.0058x over previous
#include <cuda_runtime.h>

// TritonDualLIF: x [T=16,B=32,N=196,C=512] f32, decay scalar.
// v = d*v + x[t]; vpool[t,b,c] = mean_n(pre-reset v); s = (v>=1); v = s?0:v.
// out = spikes [T,B,N,C] ++ vpool [T,B,C].
//
// R9 champion + streaming (evict-first) spike stores: write-once data leaves
// L2 promptly instead of lingering as dirty lines competing with the read
// stream. Loads keep default policy.

#define T_ 16
#define B_ 32
#define N_ 196
#define C_ 512
#define C2 (C_ / 2)        // 256 float2 per row
#define NH 4
#define NSUB 49
#define NLANES 8
#define JMAX 7             // ty==0 -> 7 rows, else 6
#define NGROUP 256         // B_ * (C2/32)

// Per-chunk partial sums: [NH][group][T*32] float2 = 4 MB.
__device__ float2   g_part[NH * NGROUP * T_ * 32];
__device__ unsigned g_ctr[NGROUP];   // parity mod 4 elects the combiner

__global__ __launch_bounds__(256, 3)
void lif_dual_kernel(const float2* __restrict__ x,
                     const float* __restrict__ decay,
                     float* __restrict__ out) {
    const int tx   = threadIdx.x;     // c2 lane 0..31
    const int ty   = threadIdx.y;     // n lane 0..7
    const int cblk = blockIdx.x;      // 0..7
    const int b    = blockIdx.y;      // 0..31
    const int z    = blockIdx.z;      // 0..3  (N chunk)
    const float d  = decay[0];

    float2* __restrict__ spikes = (float2*)out;
    float2* __restrict__ vpool  = (float2*)(out + (size_t)T_ * B_ * N_ * C_);

    __shared__ float2 red[NLANES][T_][32];  // exclusive slots, no in-loop sync
    __shared__ int    s_last;

    float2 v[JMAX];
    float2 xc[JMAX];                        // current timestep's inputs
#pragma unroll
    for (int j = 0; j < JMAX; ++j) v[j] = make_float2(0.f, 0.f);

    const unsigned c2      = (unsigned)cblk * 32u + (unsigned)tx;
    const unsigned bbase   = (unsigned)b * (N_ * C2)
                           + (unsigned)(z * NSUB + ty) * C2 + c2;
    const unsigned tstride = (unsigned)(B_ * N_ * C2);
    const int jcnt = (ty == 0) ? JMAX : (JMAX - 1);

    // Prologue: load t=0 inputs.
#pragma unroll
    for (int j = 0; j < JMAX; ++j)
        if (j < jcnt) xc[j] = x[bbase + (unsigned)(j * (NLANES * C2))];

    for (int t = 0; t < T_; ++t) {
        const unsigned tb = (unsigned)t * tstride + bbase;

        // Prefetch t+1 BEFORE consuming t.
        float2 xn[JMAX];
        if (t + 1 < T_) {
            const unsigned nb = tb + tstride;
#pragma unroll
            for (int j = 0; j < JMAX; ++j)
                if (j < jcnt) xn[j] = x[nb + (unsigned)(j * (NLANES * C2))];
        }

        float2 part = make_float2(0.f, 0.f);
#pragma unroll
        for (int j = 0; j < JMAX; ++j) {
            if (j < jcnt) {
                const unsigned idx = tb + (unsigned)(j * (NLANES * C2));
                float2 vv;
                vv.x = fmaf(d, v[j].x, xc[j].x);
                vv.y = fmaf(d, v[j].y, xc[j].y);
                part.x += vv.x;                   // pre-reset membrane
                part.y += vv.y;
                const bool fx = (vv.x >= 1.0f);
                const bool fy = (vv.y >= 1.0f);
                float2 s;
                s.x = fx ? 1.0f : 0.0f;
                s.y = fy ? 1.0f : 0.0f;
                __stcs(&spikes[idx], s);          // streaming store
                v[j].x = fx ? 0.0f : vv.x;        // hard reset
                v[j].y = fy ? 0.0f : vv.y;
            }
        }
        red[ty][t][tx] = part;                    // exclusive slot

#pragma unroll
        for (int j = 0; j < JMAX; ++j) xc[j] = xn[j];
    }

    __syncthreads();

    // Reduce 8 lanes -> chunk partial [T_*32] float2, store to scratch.
    const int tid   = ty * 32 + tx;
    const int group = b * 8 + cblk;               // 0..255
    float2* gp = &g_part[((unsigned)z * NGROUP + (unsigned)group) * (T_ * 32)];
#pragma unroll
    for (int o = 0; o < 2; ++o) {
        const int oi = tid + o * 256;             // 0..511
        const int t  = oi >> 5;
        const int cc = oi & 31;
        float2 sum = red[0][t][cc];
#pragma unroll
        for (int k = 1; k < NLANES; ++k) {
            sum.x += red[k][t][cc].x;
            sum.y += red[k][t][cc].y;
        }
        gp[oi] = sum;
    }

    __threadfence();
    __syncthreads();
    if (tid == 0) {
        const unsigned old = atomicAdd(&g_ctr[group], 1u);
        s_last = ((old & 3u) == 3u) ? 1 : 0;
    }
    __syncthreads();

    if (s_last) {
        __threadfence();   // acquire: see all chunks' scratch writes
        const float2* p0 = &g_part[((unsigned)group) * (T_ * 32)];
        const float2* p1 = &g_part[((unsigned)(NGROUP + group)) * (T_ * 32)];
        const float2* p2 = &g_part[((unsigned)(2 * NGROUP + group)) * (T_ * 32)];
        const float2* p3 = &g_part[((unsigned)(3 * NGROUP + group)) * (T_ * 32)];
#pragma unroll
        for (int o = 0; o < 2; ++o) {
            const int oi = tid + o * 256;
            const int t  = oi >> 5;
            const int cc = oi & 31;
            float2 r;
            r.x = ((p0[oi].x + p1[oi].x) + (p2[oi].x + p3[oi].x)) * (1.0f / (float)N_);
            r.y = ((p0[oi].y + p1[oi].y) + (p2[oi].y + p3[oi].y)) * (1.0f / (float)N_);
            vpool[(unsigned)t * (B_ * C2) + (unsigned)b * C2
                  + (unsigned)cblk * 32u + (unsigned)cc] = r;
        }
    }
}

extern "C" void kernel_launch(void* const* d_in, const int* in_sizes, int n_in,
                              void* d_out, int out_size) {
    const float2* x    = (const float2*)d_in[0];
    const float* decay = (const float*)d_in[1];
    float* out = (float*)d_out;

    dim3 block(32, NLANES);             // 256 threads
    dim3 grid(C2 / 32, B_, NH);         // 8 x 32 x 4 = 1024 blocks
    lif_dual_kernel<<<grid, block>>>(x, decay, out);
}